// round 11
// baseline (speedup 1.0000x reference)
#include <cuda_runtime.h>
#include <cuda_bf16.h>

// Problem constants
#define NBATCH 8
#define CIN    8
#define COUT   16
#define HW     65536        // 256*256
#define HW2    32768        // HW/2
#define NPAR   (COUT * CIN) // 128

typedef unsigned long long ull;

// Packed f32x2 FMA (Blackwell): one instruction, two fp32 lanes.
__device__ __forceinline__ ull ffma2(ull a, ull b, ull c) {
    ull d;
    asm("fma.rn.f32x2 %0, %1, %2, %3;" : "=l"(d) : "l"(a), "l"(b), "l"(c));
    return d;
}

__device__ __forceinline__ float ex2f(float v) {
    float r;
    asm("ex2.approx.f32 %0, %1;" : "=f"(r) : "f"(v));
    return r;
}

// Split a packed f32x2 into its two scalar halves (register aliasing; usually free).
__device__ __forceinline__ void unpack2(ull v, float& lo, float& hi) {
    asm("mov.b64 {%0, %1}, %2;" : "=f"(lo), "=f"(hi) : "l"(v));
}

// Per-(o,j): exp(-(x-c)^2/(2w^2)) = ex2( A*x^2 + B*x + D ), Horner: ((A*x+B)*x+D)
//   A = a, B = -2ac, D = a c^2,  a = -log2(e)/(2w^2)
struct __align__(16) Par { ull pA, pB, pD, pad; };  // each value duplicated into both f32 halves

__global__ __launch_bounds__(256, 5) void soft_hist_kernel(
    const float* __restrict__ x,        // [B][CIN][HW]
    const float* __restrict__ centers,  // [COUT][CIN]
    const float* __restrict__ widths,   // [COUT][CIN]
    float*       __restrict__ out)      // [B][COUT][HW]
{
    __shared__ Par sp[NPAR];
    int t = threadIdx.x;
    if (t < NPAR) {
        float c = centers[t];
        float w = widths[t];
        float A  = -0.72134752044448170f / (w * w);  // -log2(e)/2 / w^2
        float Bv = -2.0f * A * c;
        float D  = A * c * c;
        float2 aa = make_float2(A, A);
        float2 bb = make_float2(Bv, Bv);
        float2 dd = make_float2(D, D);
        sp[t].pA = *(ull*)&aa;
        sp[t].pB = *(ull*)&bb;
        sp[t].pD = *(ull*)&dd;
    }
    __syncthreads();

    // Each thread handles 2 consecutive spatial positions (one packed f32x2).
    int gv  = blockIdx.x * 256 + t;            // pair index in [0, B*HW2)
    int b   = gv >> 15;                        // gv / HW2
    int pos = (gv << 1) & (HW - 1);            // element offset within the image

    // 32-bit offsets throughout (max offset 8.4M elements, fits easily).
    int xoff = b * (CIN * HW) + pos;
    int ooff = b * (COUT * HW) + pos;

    // Load 8 input channels x 2 positions (LDG.64 each, independent -> MLP=8).
    ull xv[CIN];
    #pragma unroll
    for (int j = 0; j < CIN; j++)
        xv[j] = *(const ull*)(x + xoff + j * HW);

    #pragma unroll
    for (int o = 0; o < COUT; o++) {
        float s0 = 0.0f, s1 = 0.0f;
        #pragma unroll
        for (int j = 0; j < CIN; j++) {
            const Par* p = &sp[o * CIN + j];
            ulonglong2 ab = *(const ulonglong2*)p;   // LDS.128 -> {pA, pB}
            ull dd = p->pD;                          // LDS.64
            // Horner: ((A*x + B)*x + D), packed over both positions
            ull q = ffma2(ffma2(ab.x, xv[j], ab.y), xv[j], dd);
            float a0, a1;
            unpack2(q, a0, a1);
            s0 += ex2f(a0);
            s1 += ex2f(a1);
        }
        *(float2*)(out + ooff + o * HW) = make_float2(s0, s1);
    }
}

extern "C" void kernel_launch(void* const* d_in, const int* in_sizes, int n_in,
                              void* d_out, int out_size) {
    const float* x       = (const float*)d_in[0];   // [8,8,256,256]
    const float* centers = (const float*)d_in[1];   // [16,8]
    const float* widths  = (const float*)d_in[2];   // [16,8]
    float* out = (float*)d_out;                     // [8,16,256,256]

    const int pairs = NBATCH * HW2;                 // 262144
    const int block = 256;
    const int grid  = pairs / block;                // 1024
    soft_hist_kernel<<<grid, block>>>(x, centers, widths, out);
}

// round 12
// speedup vs baseline: 1.6389x; 1.6389x over previous
#include <cuda_runtime.h>
#include <cuda_bf16.h>

// Problem constants
#define NBATCH 8
#define CIN    8
#define COUT   16
#define HW     65536        // 256*256
#define HW2    32768        // HW/2
#define NPAR   (COUT * CIN) // 128

typedef unsigned long long ull;

// ---- Packed f32x2 helpers (Blackwell native) ----
__device__ __forceinline__ ull add2(ull a, ull b) {
    ull d; asm("add.rn.f32x2 %0, %1, %2;" : "=l"(d) : "l"(a), "l"(b)); return d;
}
__device__ __forceinline__ ull mul2(ull a, ull b) {
    ull d; asm("mul.rn.f32x2 %0, %1, %2;" : "=l"(d) : "l"(a), "l"(b)); return d;
}
__device__ __forceinline__ ull pack2(float lo, float hi) {
    ull r; asm("mov.b64 %0, {%1, %2};" : "=l"(r) : "f"(lo), "f"(hi)); return r;
}
__device__ __forceinline__ void unpack2(ull v, float& lo, float& hi) {
    asm("mov.b64 {%0, %1}, %2;" : "=f"(lo), "=f"(hi) : "l"(v));
}
__device__ __forceinline__ float ex2f(float v) {
    float r; asm("ex2.approx.f32 %0, %1;" : "=f"(r) : "f"(v)); return r;
}

// Per-(o,j): exp(-(x-c)^2/(2w^2)) = ex2( ((x-c)*a) * (x-c) ),  a = -log2(e)/(2w^2)
// Shared stores {-c, a} per param: one LDS.64 per inner iteration (2 SM-cyc
// broadcast) vs 4 SM-cyc of MUFU — shared bw no longer co-binding.
__global__ __launch_bounds__(256, 5) void soft_hist_kernel(
    const float* __restrict__ x,        // [B][CIN][HW]
    const float* __restrict__ centers,  // [COUT][CIN]
    const float* __restrict__ widths,   // [COUT][CIN]
    float*       __restrict__ out)      // [B][COUT][HW]
{
    __shared__ float2 sp[NPAR];
    int t = threadIdx.x;
    if (t < NPAR) {
        float c = centers[t];
        float w = widths[t];
        float a = -0.72134752044448170f / (w * w);   // -log2(e)/2 / w^2
        sp[t] = make_float2(-c, a);
    }
    __syncthreads();

    // Each thread handles 2 consecutive spatial positions (one packed f32x2).
    int gv  = blockIdx.x * 256 + t;            // pair index in [0, B*HW2)
    int b   = gv >> 15;                        // gv / HW2
    int pos = (gv << 1) & (HW - 1);            // element offset within the image

    int xoff = b * (CIN * HW) + pos;
    int ooff = b * (COUT * HW) + pos;

    // Load 8 input channels x 2 positions (LDG.64 each, independent -> MLP=8).
    ull xv[CIN];
    #pragma unroll
    for (int j = 0; j < CIN; j++)
        xv[j] = *(const ull*)(x + xoff + j * HW);

    #pragma unroll
    for (int o = 0; o < COUT; o++) {
        float s0 = 0.0f, s1 = 0.0f;
        #pragma unroll
        for (int j = 0; j < CIN; j++) {
            float2 p = sp[o * CIN + j];        // LDS.64 broadcast (2 SM-cyc)
            ull cc = pack2(p.x, p.x);          // {-c,-c}  (alu pipe)
            ull aa = pack2(p.y, p.y);          // {a,a}    (alu pipe)
            ull d  = add2(xv[j], cc);          // x - c
            ull tt = mul2(d, aa);              // (x-c)*a
            ull q  = mul2(tt, d);              // (x-c)^2*a
            float a0, a1;
            unpack2(q, a0, a1);
            s0 += ex2f(a0);
            s1 += ex2f(a1);
        }
        *(float2*)(out + ooff + o * HW) = make_float2(s0, s1);
    }
}

extern "C" void kernel_launch(void* const* d_in, const int* in_sizes, int n_in,
                              void* d_out, int out_size) {
    const float* x       = (const float*)d_in[0];   // [8,8,256,256]
    const float* centers = (const float*)d_in[1];   // [16,8]
    const float* widths  = (const float*)d_in[2];   // [16,8]
    float* out = (float*)d_out;                     // [8,16,256,256]

    const int pairs = NBATCH * HW2;                 // 262144
    const int block = 256;
    const int grid  = pairs / block;                // 1024
    soft_hist_kernel<<<grid, block>>>(x, centers, widths, out);
}